// round 15
// baseline (speedup 1.0000x reference)
#include <cuda_runtime.h>
#include <cuda_fp16.h>
#include <math.h>
#include <stdint.h>

#define IN_DIM 256
#define OUT_DIM 256
#define BATCH 2
#define MAXN 10240
#define MAXE 163840
#define SLOPE 0.2f

// ---------------- scratch (static device globals; no allocation) ----------
static __device__ float  g_src_proj[MAXN * BATCH * OUT_DIM];    // 20 MB
static __device__ __half g_vals_h[MAXN * BATCH * OUT_DIM];      // 10 MB
static __device__ __half g_nodes_h[MAXN * BATCH * IN_DIM];      // 10 MB
static __device__ __half g_WhT[2 * IN_DIM * OUT_DIM];           // W^T fp16
static __device__ float  g_sdot_part[8][MAXN * BATCH];
static __device__ float  g_tdot[MAXN * BATCH];
static __device__ float  g_denom[MAXN * BATCH];
static __device__ float  g_ex[MAXE * BATCH];
static __device__ int    g_seg_start[MAXN];
static __device__ int    g_seg_end[MAXN];
static __device__ float  g_wta[IN_DIM];
static __device__ float  g_ct;
static __device__ int    g_idx64;

// ---------------- index dtype handling -------------------------------------
__device__ __forceinline__ int IDX(const void* p, int i, int is64) {
    if (is64) return (int)(((const long long*)p)[i]);
    return ((const int*)p)[i];
}

// ---------------- fused prep: detect + ct + wta + fp16 conv + seg bounds ----
__global__ void k_prep(const void* __restrict__ usrc,
                       const float* __restrict__ Wt, const float* __restrict__ bt,
                       const float* __restrict__ Wa,
                       const float* __restrict__ nodes,
                       const float* __restrict__ Ws, const float* __restrict__ Wv,
                       const void* __restrict__ sidp,
                       int ntot, int NC, int E) {
    const int bid = blockIdx.x;
    const int t = threadIdx.x;
    if (bid == 0) {
        if (t == 0) {
            const int* p = (const int*)usrc;
            g_idx64 = (p[1] == 0 && p[3] == 0) ? 1 : 0;
        }
        __shared__ float red[256];
        red[t] = bt[t] * Wa[OUT_DIM + t];
        __syncthreads();
        for (int st = 128; st > 0; st >>= 1) {
            if (t < st) red[t] += red[t + st];
            __syncthreads();
        }
        if (t == 0) g_ct = red[0];
    } else if (bid < 33) {
        const int k = (bid - 1) * 8 + (t >> 5);
        const int lane = t & 31;
        const float* wrow = Wt + (long)k * OUT_DIM;
        float s = 0.f;
#pragma unroll
        for (int o = lane; o < OUT_DIM; o += 32) s = fmaf(wrow[o], Wa[OUT_DIM + o], s);
#pragma unroll
        for (int st = 16; st; st >>= 1) s += __shfl_xor_sync(0xFFFFFFFFu, s, st);
        if (lane == 0) g_wta[k] = s;
    } else if (bid < 33 + NC) {
        long idx = (long)(bid - 33) * 2048 + t * 8;
        if (idx + 8 <= ntot) {
            float4 v0 = *reinterpret_cast<const float4*>(nodes + idx);
            float4 v1 = *reinterpret_cast<const float4*>(nodes + idx + 4);
            __half2 h0 = __floats2half2_rn(v0.x, v0.y);
            __half2 h1 = __floats2half2_rn(v0.z, v0.w);
            __half2 h2 = __floats2half2_rn(v1.x, v1.y);
            __half2 h3 = __floats2half2_rn(v1.z, v1.w);
            uint4 o;
            o.x = *reinterpret_cast<uint32_t*>(&h0);
            o.y = *reinterpret_cast<uint32_t*>(&h1);
            o.z = *reinterpret_cast<uint32_t*>(&h2);
            o.w = *reinterpret_cast<uint32_t*>(&h3);
            *reinterpret_cast<uint4*>(g_nodes_h + idx) = o;
        }
    } else if (bid < 33 + NC + 128) {
        const int j = bid - 33 - NC;          // 0..127
        const int which = j >> 6;
        const float* __restrict__ W = which ? Wv : Ws;
        const int n = (j & 63) * 4 + (t >> 6);
        const int k = (t & 63) * 4;
        __half* dst = g_WhT + (long)which * IN_DIM * OUT_DIM + (long)n * IN_DIM + k;
#pragma unroll
        for (int q = 0; q < 4; q++)
            dst[q] = __float2half_rn(W[(long)(k + q) * OUT_DIM + n]);
    } else {
        const int e = (bid - 33 - NC - 128) * 256 + t;
        if (e < E) {
            const int* p = (const int*)usrc;
            const int my64 = (p[1] == 0 && p[3] == 0) ? 1 : 0;
            const int s = IDX(sidp, e, my64);
            if (e == 0 || IDX(sidp, e - 1, my64) != s) g_seg_start[s] = e;
            if (e == E - 1 || IDX(sidp, e + 1, my64) != s) g_seg_end[s] = e + 1;
        }
    }
}

// ---------------- fp16 mma.sync gathered GEMM (3-stage, tdot fused) ---------
#define AH_STRIDE 40
#define AH_HALVES (128 * AH_STRIDE)
#define NSTAGE 3
#define SMH_BYTES (2 * NSTAGE * AH_HALVES * 2)   // 61440 B

__device__ __forceinline__ uint32_t smem_u32(const void* p) {
    uint32_t a;
    asm("{ .reg .u64 t; cvta.to.shared.u64 t, %1; cvt.u32.u64 %0, t; }" : "=r"(a) : "l"(p));
    return a;
}
#define CP_ASYNC16(smaddr, gptr) \
    asm volatile("cp.async.ca.shared.global [%0], [%1], 16;" :: "r"(smaddr), "l"(gptr))
#define CP_COMMIT() asm volatile("cp.async.commit_group;" ::: "memory")
#define CP_WAIT2()  asm volatile("cp.async.wait_group 2;" ::: "memory")
#define CP_WAIT1()  asm volatile("cp.async.wait_group 1;" ::: "memory")
#define CP_WAIT0()  asm volatile("cp.async.wait_group 0;" ::: "memory")

__device__ __forceinline__ void mma_f16(float* c, const uint32_t* a, uint32_t b0, uint32_t b1) {
    asm volatile(
        "mma.sync.aligned.m16n8k16.row.col.f32.f16.f16.f32 "
        "{%0,%1,%2,%3}, {%4,%5,%6,%7}, {%8,%9}, {%0,%1,%2,%3};"
        : "+f"(c[0]), "+f"(c[1]), "+f"(c[2]), "+f"(c[3])
        : "r"(a[0]), "r"(a[1]), "r"(a[2]), "r"(a[3]), "r"(b0), "r"(b1));
}

__global__ __launch_bounds__(512, 2) void k_gemm_mma(
    const void* __restrict__ usrc, const void* __restrict__ utgt,
    const float* __restrict__ bs, const float* __restrict__ bv,
    const float* __restrict__ Wa, int Ms, int Mt)
{
    extern __shared__ __half smh[];
    const int which = blockIdx.z;
    const void* __restrict__ uidx = which ? utgt : usrc;
    const float* __restrict__ bias = which ? bv : bs;
    const int M = which ? Mt : Ms;

    const int t = threadIdx.x;
    const int tile_m = blockIdx.x * 128;
    const int tile_n = blockIdx.y * 128;
    if (tile_m >= M) return;
    const int is64 = g_idx64;

    const int ar = t >> 2;
    const int ak = (t & 3) * 8;
    const int mclamp = min(tile_m + ar, M - 1);
    const long gath = (long)IDX(uidx, mclamp >> 1, is64) * BATCH + (mclamp & 1);
    const __half* __restrict__ aptr = g_nodes_h + gath * IN_DIM + ak;
    const __half* __restrict__ bptr =
        g_WhT + (long)which * IN_DIM * OUT_DIM + (long)(tile_n + ar) * IN_DIM + ak;

    const uint32_t sb = smem_u32(smh);
    const uint32_t a_sm = sb + (ar * AH_STRIDE + ak) * 2;
    const uint32_t b_sm = a_sm + NSTAGE * AH_HALVES * 2;

    const int wid = t >> 5, lane = t & 31;
    const int g = lane >> 2, tg = lane & 3;
    const int wm = (wid >> 2) * 32;
    const int wn = (wid & 3) * 32;

    float acc[2][4][4];
#pragma unroll
    for (int i = 0; i < 2; i++)
#pragma unroll
        for (int j = 0; j < 4; j++)
#pragma unroll
            for (int q = 0; q < 4; q++) acc[i][j][q] = 0.f;

    CP_ASYNC16(a_sm, aptr);
    CP_ASYNC16(b_sm, bptr);
    CP_COMMIT();
    CP_ASYNC16(a_sm + AH_HALVES * 2, aptr + 32);
    CP_ASYNC16(b_sm + AH_HALVES * 2, bptr + 32);
    CP_COMMIT();

    float tacc = 0.f;

    for (int c = 0; c < 8; c++) {
        const int buf = c % 3;
        if (c < 6) {
            const int kb = (c + 2) * 32;
            const uint32_t off = ((c + 2) % 3) * (AH_HALVES * 2);
            CP_ASYNC16(a_sm + off, aptr + kb);
            CP_ASYNC16(b_sm + off, bptr + kb);
            CP_COMMIT();
            CP_WAIT2();
        } else if (c == 6) {
            CP_WAIT1();
        } else {
            CP_WAIT0();
        }
        __syncthreads();

        const __half* __restrict__ A = smh + buf * AH_HALVES;
        const __half* __restrict__ B = smh + (NSTAGE + buf) * AH_HALVES;

        if (which) {
            const __half* ap = A + ar * AH_STRIDE + ak;
            const float* wp = g_wta + c * 32 + ak;
#pragma unroll
            for (int j = 0; j < 8; j++)
                tacc = fmaf(__half2float(ap[j]), wp[j], tacc);
        }

#pragma unroll
        for (int k0 = 0; k0 < 32; k0 += 16) {
            uint32_t a0[4], a1[4];
            const int kc = k0 + 2 * tg;
            a0[0] = *reinterpret_cast<const uint32_t*>(A + (wm + g)      * AH_STRIDE + kc);
            a0[1] = *reinterpret_cast<const uint32_t*>(A + (wm + g + 8)  * AH_STRIDE + kc);
            a0[2] = *reinterpret_cast<const uint32_t*>(A + (wm + g)      * AH_STRIDE + kc + 8);
            a0[3] = *reinterpret_cast<const uint32_t*>(A + (wm + g + 8)  * AH_STRIDE + kc + 8);
            a1[0] = *reinterpret_cast<const uint32_t*>(A + (wm + 16 + g)     * AH_STRIDE + kc);
            a1[1] = *reinterpret_cast<const uint32_t*>(A + (wm + 16 + g + 8) * AH_STRIDE + kc);
            a1[2] = *reinterpret_cast<const uint32_t*>(A + (wm + 16 + g)     * AH_STRIDE + kc + 8);
            a1[3] = *reinterpret_cast<const uint32_t*>(A + (wm + 16 + g + 8) * AH_STRIDE + kc + 8);
#pragma unroll
            for (int bx = 0; bx < 4; bx++) {
                const int nrow = wn + bx * 8 + g;
                uint32_t b0 = *reinterpret_cast<const uint32_t*>(B + nrow * AH_STRIDE + kc);
                uint32_t b1 = *reinterpret_cast<const uint32_t*>(B + nrow * AH_STRIDE + kc + 8);
                mma_f16(acc[0][bx], a0, b0, b1);
                mma_f16(acc[1][bx], a1, b0, b1);
            }
        }
        __syncthreads();
    }

    if (which) {
        tacc += __shfl_xor_sync(0xFFFFFFFFu, tacc, 1);
        tacc += __shfl_xor_sync(0xFFFFFFFFu, tacc, 2);
        if (blockIdx.y == 0 && (t & 3) == 0 && tile_m + ar < M)
            g_tdot[tile_m + ar] = tacc + g_ct;
    }

    // ---- epilogue ----
    const int slot = blockIdx.y * 4 + (wid & 3);
#pragma unroll
    for (int am = 0; am < 2; am++) {
        const int m0 = tile_m + wm + am * 16 + g;
        const int m1 = m0 + 8;
        float d0 = 0.f, d1 = 0.f;
#pragma unroll
        for (int bx = 0; bx < 4; bx++) {
            const int col = tile_n + wn + bx * 8 + tg * 2;
            const float bi0 = bias[col], bi1 = bias[col + 1];
            float v00 = acc[am][bx][0] + bi0, v01 = acc[am][bx][1] + bi1;
            float v10 = acc[am][bx][2] + bi0, v11 = acc[am][bx][3] + bi1;
            if (which == 0) {
                const float wa0 = Wa[col], wa1 = Wa[col + 1];
                d0 = fmaf(v00, wa0, fmaf(v01, wa1, d0));
                d1 = fmaf(v10, wa0, fmaf(v11, wa1, d1));
                if (m0 < M)
                    *reinterpret_cast<float2*>(g_src_proj + (long)m0 * OUT_DIM + col) =
                        make_float2(v00, v01);
                if (m1 < M)
                    *reinterpret_cast<float2*>(g_src_proj + (long)m1 * OUT_DIM + col) =
                        make_float2(v10, v11);
            } else {
                if (m0 < M)
                    *reinterpret_cast<__half2*>(g_vals_h + (long)m0 * OUT_DIM + col) =
                        __floats2half2_rn(v00, v01);
                if (m1 < M)
                    *reinterpret_cast<__half2*>(g_vals_h + (long)m1 * OUT_DIM + col) =
                        __floats2half2_rn(v10, v11);
            }
        }
        if (which == 0) {
            d0 += __shfl_xor_sync(0xFFFFFFFFu, d0, 1);
            d0 += __shfl_xor_sync(0xFFFFFFFFu, d0, 2);
            d1 += __shfl_xor_sync(0xFFFFFFFFu, d1, 1);
            d1 += __shfl_xor_sync(0xFFFFFFFFu, d1, 2);
            if (tg == 0) {
                if (m0 < M) g_sdot_part[slot][m0] = d0;
                if (m1 < M) g_sdot_part[slot][m1] = d1;
            }
        }
    }
}

// ---------------- softmax: 2 nodes per warp (16 lanes each) ------------------
__global__ void k_softmax(const void* __restrict__ tidp,
                          const float* __restrict__ ba, int Ns) {
    const int warp = (blockIdx.x * blockDim.x + threadIdx.x) >> 5;
    const int lane = threadIdx.x & 31;
    const int l16 = lane & 15;
    const int n = warp * 2 + (lane >> 4);
    const bool valid = (n < Ns);
    const int is64 = g_idx64;
    const int s0 = valid ? g_seg_start[n] : 0;
    const int s1 = valid ? g_seg_end[n] : 0;

    // sdot partial reduction per 16-lane group: l16 0-7 batch0, 8-15 batch1
    float p = valid ? g_sdot_part[l16 & 7][n * 2 + (l16 >> 3)] : 0.f;
    p += __shfl_xor_sync(0xFFFFFFFFu, p, 1);
    p += __shfl_xor_sync(0xFFFFFFFFu, p, 2);
    p += __shfl_xor_sync(0xFFFFFFFFu, p, 4);
    const int gb = lane & 16;
    const float b0 = ba[0];
    const float sd0 = __shfl_sync(0xFFFFFFFFu, p, gb + 0) + b0;
    const float sd1 = __shfl_sync(0xFFFFFFFFu, p, gb + 8) + b0;

    float d0 = 0.f, d1 = 0.f;
    for (int e = s0 + l16; e < s1; e += 16) {
        int tg = IDX(tidp, e, is64);
        float sc0 = sd0 + g_tdot[tg * 2 + 0];
        float sc1 = sd1 + g_tdot[tg * 2 + 1];
        sc0 = (sc0 >= 0.f) ? sc0 : SLOPE * sc0;
        sc1 = (sc1 >= 0.f) ? sc1 : SLOPE * sc1;
        sc0 = fminf(2.f, fmaxf(-2.f, sc0));
        sc1 = fminf(2.f, fmaxf(-2.f, sc1));
        float e0 = expf(sc0), e1 = expf(sc1);
        g_ex[e * 2 + 0] = e0;
        g_ex[e * 2 + 1] = e1;
        d0 += e0;
        d1 += e1;
    }
#pragma unroll
    for (int st = 8; st; st >>= 1) {
        d0 += __shfl_xor_sync(0xFFFFFFFFu, d0, st);
        d1 += __shfl_xor_sync(0xFFFFFFFFu, d1, st);
    }
    if (valid && l16 == 0) {
        g_denom[n * 2 + 0] = d0;
        g_denom[n * 2 + 1] = d1;
    }
}

// ---------------- aggregation: 8 nodes/block, uint4 loads, hfma2 chains -----
__global__ __launch_bounds__(512) void k_agg(const void* __restrict__ sidp,
                                             const void* __restrict__ tidp,
                                             float* __restrict__ out, int Ns) {
    __shared__ __half2 wsh[2][8][16];    // broadcast (w,w) per batch
    __shared__ int ro[8][16];            // row byte offsets into g_vals_h
    __shared__ int cnts[8];
    const int t = threadIdx.x;
    const int sub = t >> 6;
    const int rest = t & 63;
    const int b = rest >> 5;
    const int o8 = rest & 31;
    const int is64 = g_idx64;

    const int n = blockIdx.x * 8 + sub;
    const bool valid = (n < Ns);
    const int s0 = valid ? g_seg_start[n] : 0;
    const int s1 = valid ? g_seg_end[n] : 0;
    if (rest == 0) cnts[sub] = s1 - s0;
    __syncthreads();
    int cmax = cnts[0];
#pragma unroll
    for (int i = 1; i < 8; i++) cmax = max(cmax, cnts[i]);

    const long outbase = ((long)n * BATCH + b) * OUT_DIM + o8 * 8;

    // 4 interleaved fp16 accumulator sets (4 half2 each)
    __half2 acch[4][4];
#pragma unroll
    for (int s = 0; s < 4; s++)
#pragma unroll
        for (int q = 0; q < 4; q++) acch[s][q] = __float2half2_rn(0.f);

    const char* __restrict__ basep =
        reinterpret_cast<const char*>(g_vals_h) + ((b << 8) + (o8 << 3)) * 2;

    for (int base = 0; base < cmax; base += 16) {
        if (t < 128) {
            const int ss = t >> 4, ii = t & 15;
            const int ns = blockIdx.x * 8 + ss;
            if (ns < Ns) {
                int e = g_seg_start[ns] + base + ii;
                if (e < g_seg_end[ns]) {
                    int j = IDX(tidp, e, is64);          // faithful bug
                    int sj = IDX(sidp, j, is64);
                    float w0 = g_ex[j * 2 + 0] / g_denom[sj * 2 + 0];
                    float w1 = g_ex[j * 2 + 1] / g_denom[sj * 2 + 1];
                    wsh[0][ss][ii] = __float2half2_rn(w0);
                    wsh[1][ss][ii] = __float2half2_rn(w1);
                    ro[ss][ii] = IDX(tidp, j, is64) * (BATCH * OUT_DIM * 2);
                } else {
                    wsh[0][ss][ii] = __float2half2_rn(0.f);
                    wsh[1][ss][ii] = __float2half2_rn(0.f);
                    ro[ss][ii] = 0;
                }
            }
        }
        __syncthreads();
        const int lim = min(16, cmax - base);
#pragma unroll 16
        for (int i = 0; i < lim; i++) {
            const __half2 wh = wsh[b][sub][i];
            uint4 h = *reinterpret_cast<const uint4*>(basep + ro[sub][i]);
            const int s = i & 3;
            acch[s][0] = __hfma2(wh, *reinterpret_cast<__half2*>(&h.x), acch[s][0]);
            acch[s][1] = __hfma2(wh, *reinterpret_cast<__half2*>(&h.y), acch[s][1]);
            acch[s][2] = __hfma2(wh, *reinterpret_cast<__half2*>(&h.z), acch[s][2]);
            acch[s][3] = __hfma2(wh, *reinterpret_cast<__half2*>(&h.w), acch[s][3]);
        }
        __syncthreads();
    }

    if (valid) {
        float4 i0 = *reinterpret_cast<const float4*>(g_src_proj + outbase);
        float4 i1 = *reinterpret_cast<const float4*>(g_src_proj + outbase + 4);
        float acc[8] = {i0.x, i0.y, i0.z, i0.w, i1.x, i1.y, i1.z, i1.w};
#pragma unroll
        for (int s = 0; s < 4; s++) {
#pragma unroll
            for (int q = 0; q < 4; q++) {
                float2 f = __half22float2(acch[s][q]);
                acc[q * 2 + 0] += f.x;
                acc[q * 2 + 1] += f.y;
            }
        }
        *reinterpret_cast<float4*>(out + outbase) =
            make_float4(acc[0], acc[1], acc[2], acc[3]);
        *reinterpret_cast<float4*>(out + outbase + 4) =
            make_float4(acc[4], acc[5], acc[6], acc[7]);
    }
}

extern "C" void kernel_launch(void* const* d_in, const int* in_sizes, int n_in,
                              void* d_out, int out_size) {
    const float* nodes = (const float*)d_in[0];
    const float* Ws    = (const float*)d_in[1];
    const float* bs    = (const float*)d_in[2];
    const float* Wt    = (const float*)d_in[3];
    const float* bt    = (const float*)d_in[4];
    const float* Wv    = (const float*)d_in[5];
    const float* bv    = (const float*)d_in[6];
    const float* Wa    = (const float*)d_in[7];
    const float* ba    = (const float*)d_in[8];
    const void* usrc   = d_in[9];
    const void* utgt   = d_in[10];
    const void* sidp   = d_in[11];
    const void* tidp   = d_in[12];

    const int Ns = in_sizes[9];
    const int Nt = in_sizes[10];
    const int E  = in_sizes[11];
    const int ntot = in_sizes[0];
    float* out = (float*)d_out;

    static int smem_set = 0;
    if (!smem_set) {
        cudaFuncSetAttribute(k_gemm_mma, cudaFuncAttributeMaxDynamicSharedMemorySize,
                             SMH_BYTES);
        smem_set = 1;
    }

    const int Ms = Ns * BATCH;
    const int Mt = Nt * BATCH;
    const int NC = (ntot + 2047) / 2048;
    const int NE = (E + 255) / 256;

    k_prep<<<33 + NC + 128 + NE, 256>>>(usrc, Wt, bt, Wa, nodes, Ws, Wv, sidp,
                                        ntot, NC, E);

    const int Mmax = (Ms > Mt) ? Ms : Mt;
    dim3 gg((Mmax + 127) / 128, OUT_DIM / 128, 2);
    k_gemm_mma<<<gg, 512, SMH_BYTES>>>(usrc, utgt, bs, bv, Wa, Ms, Mt);

    k_softmax<<<(Ns * 16 + 255) / 256, 256>>>(tidp, ba, Ns);

    k_agg<<<(Ns + 7) / 8, 512>>>(sidp, tidp, out, Ns);
}

// round 16
// speedup vs baseline: 1.0009x; 1.0009x over previous
#include <cuda_runtime.h>
#include <cuda_fp16.h>
#include <math.h>
#include <stdint.h>

#define IN_DIM 256
#define OUT_DIM 256
#define BATCH 2
#define MAXN 10240
#define MAXE 163840
#define SLOPE 0.2f

// ---------------- scratch (static device globals; no allocation) ----------
static __device__ float  g_src_proj[MAXN * BATCH * OUT_DIM];    // 20 MB
static __device__ __half g_vals_h[MAXN * BATCH * OUT_DIM];      // 10 MB
static __device__ __half g_nodes_h[MAXN * BATCH * IN_DIM];      // 10 MB
static __device__ __half g_WhT[2 * IN_DIM * OUT_DIM];           // W^T fp16
static __device__ float  g_sdot_part[8][MAXN * BATCH];
static __device__ float  g_tdot[MAXN * BATCH];
static __device__ float  g_denom[MAXN * BATCH];
static __device__ float  g_ex[MAXE * BATCH];
static __device__ int    g_seg_start[MAXN];
static __device__ int    g_seg_end[MAXN];
static __device__ float  g_wta[IN_DIM];
static __device__ float  g_ct;
static __device__ int    g_idx64;

// ---------------- index dtype handling -------------------------------------
__device__ __forceinline__ int IDX(const void* p, int i, int is64) {
    if (is64) return (int)(((const long long*)p)[i]);
    return ((const int*)p)[i];
}

// ---------------- fused prep: detect + ct + wta + fp16 conv + seg bounds ----
__global__ void k_prep(const void* __restrict__ usrc,
                       const float* __restrict__ Wt, const float* __restrict__ bt,
                       const float* __restrict__ Wa,
                       const float* __restrict__ nodes,
                       const float* __restrict__ Ws, const float* __restrict__ Wv,
                       const void* __restrict__ sidp,
                       int ntot, int NC, int E) {
    const int bid = blockIdx.x;
    const int t = threadIdx.x;
    if (bid == 0) {
        if (t == 0) {
            const int* p = (const int*)usrc;
            g_idx64 = (p[1] == 0 && p[3] == 0) ? 1 : 0;
        }
        __shared__ float red[256];
        red[t] = bt[t] * Wa[OUT_DIM + t];
        __syncthreads();
        for (int st = 128; st > 0; st >>= 1) {
            if (t < st) red[t] += red[t + st];
            __syncthreads();
        }
        if (t == 0) g_ct = red[0];
    } else if (bid < 33) {
        const int k = (bid - 1) * 8 + (t >> 5);
        const int lane = t & 31;
        const float* wrow = Wt + (long)k * OUT_DIM;
        float s = 0.f;
#pragma unroll
        for (int o = lane; o < OUT_DIM; o += 32) s = fmaf(wrow[o], Wa[OUT_DIM + o], s);
#pragma unroll
        for (int st = 16; st; st >>= 1) s += __shfl_xor_sync(0xFFFFFFFFu, s, st);
        if (lane == 0) g_wta[k] = s;
    } else if (bid < 33 + NC) {
        long idx = (long)(bid - 33) * 2048 + t * 8;
        if (idx + 8 <= ntot) {
            float4 v0 = *reinterpret_cast<const float4*>(nodes + idx);
            float4 v1 = *reinterpret_cast<const float4*>(nodes + idx + 4);
            __half2 h0 = __floats2half2_rn(v0.x, v0.y);
            __half2 h1 = __floats2half2_rn(v0.z, v0.w);
            __half2 h2 = __floats2half2_rn(v1.x, v1.y);
            __half2 h3 = __floats2half2_rn(v1.z, v1.w);
            uint4 o;
            o.x = *reinterpret_cast<uint32_t*>(&h0);
            o.y = *reinterpret_cast<uint32_t*>(&h1);
            o.z = *reinterpret_cast<uint32_t*>(&h2);
            o.w = *reinterpret_cast<uint32_t*>(&h3);
            *reinterpret_cast<uint4*>(g_nodes_h + idx) = o;
        }
    } else if (bid < 33 + NC + 128) {
        const int j = bid - 33 - NC;          // 0..127
        const int which = j >> 6;
        const float* __restrict__ W = which ? Wv : Ws;
        const int n = (j & 63) * 4 + (t >> 6);
        const int k = (t & 63) * 4;
        __half* dst = g_WhT + (long)which * IN_DIM * OUT_DIM + (long)n * IN_DIM + k;
#pragma unroll
        for (int q = 0; q < 4; q++)
            dst[q] = __float2half_rn(W[(long)(k + q) * OUT_DIM + n]);
    } else {
        const int e = (bid - 33 - NC - 128) * 256 + t;
        if (e < E) {
            const int* p = (const int*)usrc;
            const int my64 = (p[1] == 0 && p[3] == 0) ? 1 : 0;
            const int s = IDX(sidp, e, my64);
            if (e == 0 || IDX(sidp, e - 1, my64) != s) g_seg_start[s] = e;
            if (e == E - 1 || IDX(sidp, e + 1, my64) != s) g_seg_end[s] = e + 1;
        }
    }
}

// ---------------- fp16 mma.sync gathered GEMM (3-stage, tdot fused) ---------
#define AH_STRIDE 40
#define AH_HALVES (128 * AH_STRIDE)
#define NSTAGE 3
#define SMH_BYTES (2 * NSTAGE * AH_HALVES * 2)   // 61440 B

__device__ __forceinline__ uint32_t smem_u32(const void* p) {
    uint32_t a;
    asm("{ .reg .u64 t; cvta.to.shared.u64 t, %1; cvt.u32.u64 %0, t; }" : "=r"(a) : "l"(p));
    return a;
}
#define CP_ASYNC16(smaddr, gptr) \
    asm volatile("cp.async.ca.shared.global [%0], [%1], 16;" :: "r"(smaddr), "l"(gptr))
#define CP_COMMIT() asm volatile("cp.async.commit_group;" ::: "memory")
#define CP_WAIT2()  asm volatile("cp.async.wait_group 2;" ::: "memory")
#define CP_WAIT1()  asm volatile("cp.async.wait_group 1;" ::: "memory")
#define CP_WAIT0()  asm volatile("cp.async.wait_group 0;" ::: "memory")

__device__ __forceinline__ void mma_f16(float* c, const uint32_t* a, uint32_t b0, uint32_t b1) {
    asm volatile(
        "mma.sync.aligned.m16n8k16.row.col.f32.f16.f16.f32 "
        "{%0,%1,%2,%3}, {%4,%5,%6,%7}, {%8,%9}, {%0,%1,%2,%3};"
        : "+f"(c[0]), "+f"(c[1]), "+f"(c[2]), "+f"(c[3])
        : "r"(a[0]), "r"(a[1]), "r"(a[2]), "r"(a[3]), "r"(b0), "r"(b1));
}

__global__ __launch_bounds__(512, 2) void k_gemm_mma(
    const void* __restrict__ usrc, const void* __restrict__ utgt,
    const float* __restrict__ bs, const float* __restrict__ bv,
    const float* __restrict__ Wa, int Ms, int Mt)
{
    extern __shared__ __half smh[];
    const int which = blockIdx.z;
    const void* __restrict__ uidx = which ? utgt : usrc;
    const float* __restrict__ bias = which ? bv : bs;
    const int M = which ? Mt : Ms;

    const int t = threadIdx.x;
    const int tile_m = blockIdx.x * 128;
    const int tile_n = blockIdx.y * 128;
    if (tile_m >= M) return;
    const int is64 = g_idx64;

    const int ar = t >> 2;
    const int ak = (t & 3) * 8;
    const int mclamp = min(tile_m + ar, M - 1);
    const long gath = (long)IDX(uidx, mclamp >> 1, is64) * BATCH + (mclamp & 1);
    const __half* __restrict__ aptr = g_nodes_h + gath * IN_DIM + ak;
    const __half* __restrict__ bptr =
        g_WhT + (long)which * IN_DIM * OUT_DIM + (long)(tile_n + ar) * IN_DIM + ak;

    const uint32_t sb = smem_u32(smh);
    const uint32_t a_sm = sb + (ar * AH_STRIDE + ak) * 2;
    const uint32_t b_sm = a_sm + NSTAGE * AH_HALVES * 2;

    const int wid = t >> 5, lane = t & 31;
    const int g = lane >> 2, tg = lane & 3;
    const int wm = (wid >> 2) * 32;
    const int wn = (wid & 3) * 32;

    float acc[2][4][4];
#pragma unroll
    for (int i = 0; i < 2; i++)
#pragma unroll
        for (int j = 0; j < 4; j++)
#pragma unroll
            for (int q = 0; q < 4; q++) acc[i][j][q] = 0.f;

    CP_ASYNC16(a_sm, aptr);
    CP_ASYNC16(b_sm, bptr);
    CP_COMMIT();
    CP_ASYNC16(a_sm + AH_HALVES * 2, aptr + 32);
    CP_ASYNC16(b_sm + AH_HALVES * 2, bptr + 32);
    CP_COMMIT();

    float tacc = 0.f;

    for (int c = 0; c < 8; c++) {
        const int buf = c % 3;
        if (c < 6) {
            const int kb = (c + 2) * 32;
            const uint32_t off = ((c + 2) % 3) * (AH_HALVES * 2);
            CP_ASYNC16(a_sm + off, aptr + kb);
            CP_ASYNC16(b_sm + off, bptr + kb);
            CP_COMMIT();
            CP_WAIT2();
        } else if (c == 6) {
            CP_WAIT1();
        } else {
            CP_WAIT0();
        }
        __syncthreads();

        const __half* __restrict__ A = smh + buf * AH_HALVES;
        const __half* __restrict__ B = smh + (NSTAGE + buf) * AH_HALVES;

        if (which) {
            const __half* ap = A + ar * AH_STRIDE + ak;
            const float* wp = g_wta + c * 32 + ak;
#pragma unroll
            for (int j = 0; j < 8; j++)
                tacc = fmaf(__half2float(ap[j]), wp[j], tacc);
        }

#pragma unroll
        for (int k0 = 0; k0 < 32; k0 += 16) {
            uint32_t a0[4], a1[4];
            const int kc = k0 + 2 * tg;
            a0[0] = *reinterpret_cast<const uint32_t*>(A + (wm + g)      * AH_STRIDE + kc);
            a0[1] = *reinterpret_cast<const uint32_t*>(A + (wm + g + 8)  * AH_STRIDE + kc);
            a0[2] = *reinterpret_cast<const uint32_t*>(A + (wm + g)      * AH_STRIDE + kc + 8);
            a0[3] = *reinterpret_cast<const uint32_t*>(A + (wm + g + 8)  * AH_STRIDE + kc + 8);
            a1[0] = *reinterpret_cast<const uint32_t*>(A + (wm + 16 + g)     * AH_STRIDE + kc);
            a1[1] = *reinterpret_cast<const uint32_t*>(A + (wm + 16 + g + 8) * AH_STRIDE + kc);
            a1[2] = *reinterpret_cast<const uint32_t*>(A + (wm + 16 + g)     * AH_STRIDE + kc + 8);
            a1[3] = *reinterpret_cast<const uint32_t*>(A + (wm + 16 + g + 8) * AH_STRIDE + kc + 8);
#pragma unroll
            for (int bx = 0; bx < 4; bx++) {
                const int nrow = wn + bx * 8 + g;
                uint32_t b0 = *reinterpret_cast<const uint32_t*>(B + nrow * AH_STRIDE + kc);
                uint32_t b1 = *reinterpret_cast<const uint32_t*>(B + nrow * AH_STRIDE + kc + 8);
                mma_f16(acc[0][bx], a0, b0, b1);
                mma_f16(acc[1][bx], a1, b0, b1);
            }
        }
        __syncthreads();
    }

    if (which) {
        tacc += __shfl_xor_sync(0xFFFFFFFFu, tacc, 1);
        tacc += __shfl_xor_sync(0xFFFFFFFFu, tacc, 2);
        if (blockIdx.y == 0 && (t & 3) == 0 && tile_m + ar < M)
            g_tdot[tile_m + ar] = tacc + g_ct;
    }

    // ---- epilogue ----
    const int slot = blockIdx.y * 4 + (wid & 3);
#pragma unroll
    for (int am = 0; am < 2; am++) {
        const int m0 = tile_m + wm + am * 16 + g;
        const int m1 = m0 + 8;
        float d0 = 0.f, d1 = 0.f;
#pragma unroll
        for (int bx = 0; bx < 4; bx++) {
            const int col = tile_n + wn + bx * 8 + tg * 2;
            const float bi0 = bias[col], bi1 = bias[col + 1];
            float v00 = acc[am][bx][0] + bi0, v01 = acc[am][bx][1] + bi1;
            float v10 = acc[am][bx][2] + bi0, v11 = acc[am][bx][3] + bi1;
            if (which == 0) {
                const float wa0 = Wa[col], wa1 = Wa[col + 1];
                d0 = fmaf(v00, wa0, fmaf(v01, wa1, d0));
                d1 = fmaf(v10, wa0, fmaf(v11, wa1, d1));
                if (m0 < M)
                    *reinterpret_cast<float2*>(g_src_proj + (long)m0 * OUT_DIM + col) =
                        make_float2(v00, v01);
                if (m1 < M)
                    *reinterpret_cast<float2*>(g_src_proj + (long)m1 * OUT_DIM + col) =
                        make_float2(v10, v11);
            } else {
                if (m0 < M)
                    *reinterpret_cast<__half2*>(g_vals_h + (long)m0 * OUT_DIM + col) =
                        __floats2half2_rn(v00, v01);
                if (m1 < M)
                    *reinterpret_cast<__half2*>(g_vals_h + (long)m1 * OUT_DIM + col) =
                        __floats2half2_rn(v10, v11);
            }
        }
        if (which == 0) {
            d0 += __shfl_xor_sync(0xFFFFFFFFu, d0, 1);
            d0 += __shfl_xor_sync(0xFFFFFFFFu, d0, 2);
            d1 += __shfl_xor_sync(0xFFFFFFFFu, d1, 1);
            d1 += __shfl_xor_sync(0xFFFFFFFFu, d1, 2);
            if (tg == 0) {
                if (m0 < M) g_sdot_part[slot][m0] = d0;
                if (m1 < M) g_sdot_part[slot][m1] = d1;
            }
        }
    }
}

// ---------------- softmax: 2 nodes per warp (16 lanes each) ------------------
__global__ void k_softmax(const void* __restrict__ tidp,
                          const float* __restrict__ ba, int Ns) {
    const int warp = (blockIdx.x * blockDim.x + threadIdx.x) >> 5;
    const int lane = threadIdx.x & 31;
    const int l16 = lane & 15;
    const int n = warp * 2 + (lane >> 4);
    const bool valid = (n < Ns);
    const int is64 = g_idx64;
    const int s0 = valid ? g_seg_start[n] : 0;
    const int s1 = valid ? g_seg_end[n] : 0;

    // sdot partial reduction per 16-lane group: l16 0-7 batch0, 8-15 batch1
    float p = valid ? g_sdot_part[l16 & 7][n * 2 + (l16 >> 3)] : 0.f;
    p += __shfl_xor_sync(0xFFFFFFFFu, p, 1);
    p += __shfl_xor_sync(0xFFFFFFFFu, p, 2);
    p += __shfl_xor_sync(0xFFFFFFFFu, p, 4);
    const int gb = lane & 16;
    const float b0 = ba[0];
    const float sd0 = __shfl_sync(0xFFFFFFFFu, p, gb + 0) + b0;
    const float sd1 = __shfl_sync(0xFFFFFFFFu, p, gb + 8) + b0;

    float d0 = 0.f, d1 = 0.f;
    for (int e = s0 + l16; e < s1; e += 16) {
        int tg = IDX(tidp, e, is64);
        float sc0 = sd0 + g_tdot[tg * 2 + 0];
        float sc1 = sd1 + g_tdot[tg * 2 + 1];
        sc0 = (sc0 >= 0.f) ? sc0 : SLOPE * sc0;
        sc1 = (sc1 >= 0.f) ? sc1 : SLOPE * sc1;
        sc0 = fminf(2.f, fmaxf(-2.f, sc0));
        sc1 = fminf(2.f, fmaxf(-2.f, sc1));
        float e0 = expf(sc0), e1 = expf(sc1);
        g_ex[e * 2 + 0] = e0;
        g_ex[e * 2 + 1] = e1;
        d0 += e0;
        d1 += e1;
    }
#pragma unroll
    for (int st = 8; st; st >>= 1) {
        d0 += __shfl_xor_sync(0xFFFFFFFFu, d0, st);
        d1 += __shfl_xor_sync(0xFFFFFFFFu, d1, st);
    }
    if (valid && l16 == 0) {
        g_denom[n * 2 + 0] = d0;
        g_denom[n * 2 + 1] = d1;
    }
}

// ---------------- aggregation: 8 nodes/block, uint4 loads, hfma2 chains -----
__global__ __launch_bounds__(512) void k_agg(const void* __restrict__ sidp,
                                             const void* __restrict__ tidp,
                                             float* __restrict__ out, int Ns) {
    __shared__ __half2 wsh[2][8][16];    // broadcast (w,w) per batch
    __shared__ int ro[8][16];            // row byte offsets into g_vals_h
    __shared__ int cnts[8];
    const int t = threadIdx.x;
    const int sub = t >> 6;
    const int rest = t & 63;
    const int b = rest >> 5;
    const int o8 = rest & 31;
    const int is64 = g_idx64;

    const int n = blockIdx.x * 8 + sub;
    const bool valid = (n < Ns);
    const int s0 = valid ? g_seg_start[n] : 0;
    const int s1 = valid ? g_seg_end[n] : 0;
    if (rest == 0) cnts[sub] = s1 - s0;
    __syncthreads();
    int cmax = cnts[0];
#pragma unroll
    for (int i = 1; i < 8; i++) cmax = max(cmax, cnts[i]);

    const long outbase = ((long)n * BATCH + b) * OUT_DIM + o8 * 8;

    // 4 interleaved fp16 accumulator sets (4 half2 each)
    __half2 acch[4][4];
#pragma unroll
    for (int s = 0; s < 4; s++)
#pragma unroll
        for (int q = 0; q < 4; q++) acch[s][q] = __float2half2_rn(0.f);

    const char* __restrict__ basep =
        reinterpret_cast<const char*>(g_vals_h) + ((b << 8) + (o8 << 3)) * 2;

    for (int base = 0; base < cmax; base += 16) {
        if (t < 128) {
            const int ss = t >> 4, ii = t & 15;
            const int ns = blockIdx.x * 8 + ss;
            if (ns < Ns) {
                int e = g_seg_start[ns] + base + ii;
                if (e < g_seg_end[ns]) {
                    int j = IDX(tidp, e, is64);          // faithful bug
                    int sj = IDX(sidp, j, is64);
                    float w0 = g_ex[j * 2 + 0] / g_denom[sj * 2 + 0];
                    float w1 = g_ex[j * 2 + 1] / g_denom[sj * 2 + 1];
                    wsh[0][ss][ii] = __float2half2_rn(w0);
                    wsh[1][ss][ii] = __float2half2_rn(w1);
                    ro[ss][ii] = IDX(tidp, j, is64) * (BATCH * OUT_DIM * 2);
                } else {
                    wsh[0][ss][ii] = __float2half2_rn(0.f);
                    wsh[1][ss][ii] = __float2half2_rn(0.f);
                    ro[ss][ii] = 0;
                }
            }
        }
        __syncthreads();
        const int lim = min(16, cmax - base);
#pragma unroll 16
        for (int i = 0; i < lim; i++) {
            const __half2 wh = wsh[b][sub][i];
            uint4 h = *reinterpret_cast<const uint4*>(basep + ro[sub][i]);
            const int s = i & 3;
            acch[s][0] = __hfma2(wh, *reinterpret_cast<__half2*>(&h.x), acch[s][0]);
            acch[s][1] = __hfma2(wh, *reinterpret_cast<__half2*>(&h.y), acch[s][1]);
            acch[s][2] = __hfma2(wh, *reinterpret_cast<__half2*>(&h.z), acch[s][2]);
            acch[s][3] = __hfma2(wh, *reinterpret_cast<__half2*>(&h.w), acch[s][3]);
        }
        __syncthreads();
    }

    if (valid) {
        float4 i0 = *reinterpret_cast<const float4*>(g_src_proj + outbase);
        float4 i1 = *reinterpret_cast<const float4*>(g_src_proj + outbase + 4);
        float acc[8] = {i0.x, i0.y, i0.z, i0.w, i1.x, i1.y, i1.z, i1.w};
#pragma unroll
        for (int s = 0; s < 4; s++) {
#pragma unroll
            for (int q = 0; q < 4; q++) {
                float2 f = __half22float2(acch[s][q]);
                acc[q * 2 + 0] += f.x;
                acc[q * 2 + 1] += f.y;
            }
        }
        *reinterpret_cast<float4*>(out + outbase) =
            make_float4(acc[0], acc[1], acc[2], acc[3]);
        *reinterpret_cast<float4*>(out + outbase + 4) =
            make_float4(acc[4], acc[5], acc[6], acc[7]);
    }
}

extern "C" void kernel_launch(void* const* d_in, const int* in_sizes, int n_in,
                              void* d_out, int out_size) {
    const float* nodes = (const float*)d_in[0];
    const float* Ws    = (const float*)d_in[1];
    const float* bs    = (const float*)d_in[2];
    const float* Wt    = (const float*)d_in[3];
    const float* bt    = (const float*)d_in[4];
    const float* Wv    = (const float*)d_in[5];
    const float* bv    = (const float*)d_in[6];
    const float* Wa    = (const float*)d_in[7];
    const float* ba    = (const float*)d_in[8];
    const void* usrc   = d_in[9];
    const void* utgt   = d_in[10];
    const void* sidp   = d_in[11];
    const void* tidp   = d_in[12];

    const int Ns = in_sizes[9];
    const int Nt = in_sizes[10];
    const int E  = in_sizes[11];
    const int ntot = in_sizes[0];
    float* out = (float*)d_out;

    static int smem_set = 0;
    if (!smem_set) {
        cudaFuncSetAttribute(k_gemm_mma, cudaFuncAttributeMaxDynamicSharedMemorySize,
                             SMH_BYTES);
        smem_set = 1;
    }

    const int Ms = Ns * BATCH;
    const int Mt = Nt * BATCH;
    const int NC = (ntot + 2047) / 2048;
    const int NE = (E + 255) / 256;

    k_prep<<<33 + NC + 128 + NE, 256>>>(usrc, Wt, bt, Wa, nodes, Ws, Wv, sidp,
                                        ntot, NC, E);

    const int Mmax = (Ms > Mt) ? Ms : Mt;
    dim3 gg((Mmax + 127) / 128, OUT_DIM / 128, 2);
    k_gemm_mma<<<gg, 512, SMH_BYTES>>>(usrc, utgt, bs, bv, Wa, Ms, Mt);

    k_softmax<<<(Ns * 16 + 255) / 256, 256>>>(tidp, ba, Ns);

    k_agg<<<(Ns + 7) / 8, 512>>>(sidp, tidp, out, Ns);
}

// round 17
// speedup vs baseline: 1.0098x; 1.0089x over previous
#include <cuda_runtime.h>
#include <cuda_fp16.h>
#include <math.h>
#include <stdint.h>

#define IN_DIM 256
#define OUT_DIM 256
#define BATCH 2
#define MAXN 10240
#define MAXE 163840
#define SLOPE 0.2f

// ---------------- scratch (static device globals; no allocation) ----------
static __device__ float  g_src_proj[MAXN * BATCH * OUT_DIM];    // 20 MB
static __device__ __half g_vals_h[MAXN * BATCH * OUT_DIM];      // 10 MB
static __device__ __half g_nodes_h[MAXN * BATCH * IN_DIM];      // 10 MB
static __device__ __half g_WhT[2 * IN_DIM * OUT_DIM];           // W^T fp16
static __device__ float  g_sdot_part[8][MAXN * BATCH];
static __device__ float  g_tdot[MAXN * BATCH];
static __device__ float  g_denom[MAXN * BATCH];
static __device__ float  g_ex[MAXE * BATCH];
static __device__ int    g_seg_start[MAXN];
static __device__ int    g_seg_end[MAXN];
static __device__ float  g_wta[IN_DIM];
static __device__ float  g_ct;
static __device__ int    g_idx64;

// ---------------- index dtype handling -------------------------------------
__device__ __forceinline__ int IDX(const void* p, int i, int is64) {
    if (is64) return (int)(((const long long*)p)[i]);
    return ((const int*)p)[i];
}

// ---------------- fused prep: detect + ct + wta + fp16 conv + seg bounds ----
__global__ void k_prep(const void* __restrict__ usrc,
                       const float* __restrict__ Wt, const float* __restrict__ bt,
                       const float* __restrict__ Wa,
                       const float* __restrict__ nodes,
                       const float* __restrict__ Ws, const float* __restrict__ Wv,
                       const void* __restrict__ sidp,
                       int ntot, int NC, int E) {
    const int bid = blockIdx.x;
    const int t = threadIdx.x;
    if (bid == 0) {
        if (t == 0) {
            const int* p = (const int*)usrc;
            g_idx64 = (p[1] == 0 && p[3] == 0) ? 1 : 0;
        }
        __shared__ float red[256];
        red[t] = bt[t] * Wa[OUT_DIM + t];
        __syncthreads();
        for (int st = 128; st > 0; st >>= 1) {
            if (t < st) red[t] += red[t + st];
            __syncthreads();
        }
        if (t == 0) g_ct = red[0];
    } else if (bid < 33) {
        const int k = (bid - 1) * 8 + (t >> 5);
        const int lane = t & 31;
        const float* wrow = Wt + (long)k * OUT_DIM;
        float s = 0.f;
#pragma unroll
        for (int o = lane; o < OUT_DIM; o += 32) s = fmaf(wrow[o], Wa[OUT_DIM + o], s);
#pragma unroll
        for (int st = 16; st; st >>= 1) s += __shfl_xor_sync(0xFFFFFFFFu, s, st);
        if (lane == 0) g_wta[k] = s;
    } else if (bid < 33 + NC) {
        long idx = (long)(bid - 33) * 2048 + t * 8;
        if (idx + 8 <= ntot) {
            float4 v0 = *reinterpret_cast<const float4*>(nodes + idx);
            float4 v1 = *reinterpret_cast<const float4*>(nodes + idx + 4);
            __half2 h0 = __floats2half2_rn(v0.x, v0.y);
            __half2 h1 = __floats2half2_rn(v0.z, v0.w);
            __half2 h2 = __floats2half2_rn(v1.x, v1.y);
            __half2 h3 = __floats2half2_rn(v1.z, v1.w);
            uint4 o;
            o.x = *reinterpret_cast<uint32_t*>(&h0);
            o.y = *reinterpret_cast<uint32_t*>(&h1);
            o.z = *reinterpret_cast<uint32_t*>(&h2);
            o.w = *reinterpret_cast<uint32_t*>(&h3);
            *reinterpret_cast<uint4*>(g_nodes_h + idx) = o;
        }
    } else if (bid < 33 + NC + 128) {
        const int j = bid - 33 - NC;          // 0..127
        const int which = j >> 6;
        const float* __restrict__ W = which ? Wv : Ws;
        const int n = (j & 63) * 4 + (t >> 6);
        const int k = (t & 63) * 4;
        __half* dst = g_WhT + (long)which * IN_DIM * OUT_DIM + (long)n * IN_DIM + k;
#pragma unroll
        for (int q = 0; q < 4; q++)
            dst[q] = __float2half_rn(W[(long)(k + q) * OUT_DIM + n]);
    } else {
        const int e = (bid - 33 - NC - 128) * 256 + t;
        if (e < E) {
            const int* p = (const int*)usrc;
            const int my64 = (p[1] == 0 && p[3] == 0) ? 1 : 0;
            const int s = IDX(sidp, e, my64);
            if (e == 0 || IDX(sidp, e - 1, my64) != s) g_seg_start[s] = e;
            if (e == E - 1 || IDX(sidp, e + 1, my64) != s) g_seg_end[s] = e + 1;
        }
    }
}

// ---------------- fp16 mma.sync gathered GEMM (3-stage, tdot fused) ---------
#define AH_STRIDE 40
#define AH_HALVES (128 * AH_STRIDE)
#define NSTAGE 3
#define SMH_BYTES (2 * NSTAGE * AH_HALVES * 2)   // 61440 B

__device__ __forceinline__ uint32_t smem_u32(const void* p) {
    uint32_t a;
    asm("{ .reg .u64 t; cvta.to.shared.u64 t, %1; cvt.u32.u64 %0, t; }" : "=r"(a) : "l"(p));
    return a;
}
#define CP_ASYNC16(smaddr, gptr) \
    asm volatile("cp.async.ca.shared.global [%0], [%1], 16;" :: "r"(smaddr), "l"(gptr))
#define CP_COMMIT() asm volatile("cp.async.commit_group;" ::: "memory")
#define CP_WAIT2()  asm volatile("cp.async.wait_group 2;" ::: "memory")
#define CP_WAIT1()  asm volatile("cp.async.wait_group 1;" ::: "memory")
#define CP_WAIT0()  asm volatile("cp.async.wait_group 0;" ::: "memory")

__device__ __forceinline__ void mma_f16(float* c, const uint32_t* a, uint32_t b0, uint32_t b1) {
    asm volatile(
        "mma.sync.aligned.m16n8k16.row.col.f32.f16.f16.f32 "
        "{%0,%1,%2,%3}, {%4,%5,%6,%7}, {%8,%9}, {%0,%1,%2,%3};"
        : "+f"(c[0]), "+f"(c[1]), "+f"(c[2]), "+f"(c[3])
        : "r"(a[0]), "r"(a[1]), "r"(a[2]), "r"(a[3]), "r"(b0), "r"(b1));
}

__global__ __launch_bounds__(512, 2) void k_gemm_mma(
    const void* __restrict__ usrc, const void* __restrict__ utgt,
    const float* __restrict__ bs, const float* __restrict__ bv,
    const float* __restrict__ Wa, int Ms, int Mt)
{
    extern __shared__ __half smh[];
    const int which = blockIdx.z;
    const void* __restrict__ uidx = which ? utgt : usrc;
    const float* __restrict__ bias = which ? bv : bs;
    const int M = which ? Mt : Ms;

    const int t = threadIdx.x;
    const int tile_m = blockIdx.x * 128;
    const int tile_n = blockIdx.y * 128;
    if (tile_m >= M) return;
    const int is64 = g_idx64;

    const int ar = t >> 2;
    const int ak = (t & 3) * 8;
    const int mclamp = min(tile_m + ar, M - 1);
    const long gath = (long)IDX(uidx, mclamp >> 1, is64) * BATCH + (mclamp & 1);
    const __half* __restrict__ aptr = g_nodes_h + gath * IN_DIM + ak;
    const __half* __restrict__ bptr =
        g_WhT + (long)which * IN_DIM * OUT_DIM + (long)(tile_n + ar) * IN_DIM + ak;

    const uint32_t sb = smem_u32(smh);
    const uint32_t a_sm = sb + (ar * AH_STRIDE + ak) * 2;
    const uint32_t b_sm = a_sm + NSTAGE * AH_HALVES * 2;

    const int wid = t >> 5, lane = t & 31;
    const int g = lane >> 2, tg = lane & 3;
    const int wm = (wid >> 2) * 32;
    const int wn = (wid & 3) * 32;

    float acc[2][4][4];
#pragma unroll
    for (int i = 0; i < 2; i++)
#pragma unroll
        for (int j = 0; j < 4; j++)
#pragma unroll
            for (int q = 0; q < 4; q++) acc[i][j][q] = 0.f;

    CP_ASYNC16(a_sm, aptr);
    CP_ASYNC16(b_sm, bptr);
    CP_COMMIT();
    CP_ASYNC16(a_sm + AH_HALVES * 2, aptr + 32);
    CP_ASYNC16(b_sm + AH_HALVES * 2, bptr + 32);
    CP_COMMIT();

    float tacc = 0.f;

    for (int c = 0; c < 8; c++) {
        const int buf = c % 3;
        if (c < 6) {
            const int kb = (c + 2) * 32;
            const uint32_t off = ((c + 2) % 3) * (AH_HALVES * 2);
            CP_ASYNC16(a_sm + off, aptr + kb);
            CP_ASYNC16(b_sm + off, bptr + kb);
            CP_COMMIT();
            CP_WAIT2();
        } else if (c == 6) {
            CP_WAIT1();
        } else {
            CP_WAIT0();
        }
        __syncthreads();

        const __half* __restrict__ A = smh + buf * AH_HALVES;
        const __half* __restrict__ B = smh + (NSTAGE + buf) * AH_HALVES;

        if (which) {
            const __half* ap = A + ar * AH_STRIDE + ak;
            const float* wp = g_wta + c * 32 + ak;
#pragma unroll
            for (int j = 0; j < 8; j++)
                tacc = fmaf(__half2float(ap[j]), wp[j], tacc);
        }

#pragma unroll
        for (int k0 = 0; k0 < 32; k0 += 16) {
            uint32_t a0[4], a1[4];
            const int kc = k0 + 2 * tg;
            a0[0] = *reinterpret_cast<const uint32_t*>(A + (wm + g)      * AH_STRIDE + kc);
            a0[1] = *reinterpret_cast<const uint32_t*>(A + (wm + g + 8)  * AH_STRIDE + kc);
            a0[2] = *reinterpret_cast<const uint32_t*>(A + (wm + g)      * AH_STRIDE + kc + 8);
            a0[3] = *reinterpret_cast<const uint32_t*>(A + (wm + g + 8)  * AH_STRIDE + kc + 8);
            a1[0] = *reinterpret_cast<const uint32_t*>(A + (wm + 16 + g)     * AH_STRIDE + kc);
            a1[1] = *reinterpret_cast<const uint32_t*>(A + (wm + 16 + g + 8) * AH_STRIDE + kc);
            a1[2] = *reinterpret_cast<const uint32_t*>(A + (wm + 16 + g)     * AH_STRIDE + kc + 8);
            a1[3] = *reinterpret_cast<const uint32_t*>(A + (wm + 16 + g + 8) * AH_STRIDE + kc + 8);
#pragma unroll
            for (int bx = 0; bx < 4; bx++) {
                const int nrow = wn + bx * 8 + g;
                uint32_t b0 = *reinterpret_cast<const uint32_t*>(B + nrow * AH_STRIDE + kc);
                uint32_t b1 = *reinterpret_cast<const uint32_t*>(B + nrow * AH_STRIDE + kc + 8);
                mma_f16(acc[0][bx], a0, b0, b1);
                mma_f16(acc[1][bx], a1, b0, b1);
            }
        }
        __syncthreads();
    }

    if (which) {
        tacc += __shfl_xor_sync(0xFFFFFFFFu, tacc, 1);
        tacc += __shfl_xor_sync(0xFFFFFFFFu, tacc, 2);
        if (blockIdx.y == 0 && (t & 3) == 0 && tile_m + ar < M)
            g_tdot[tile_m + ar] = tacc + g_ct;
    }

    // ---- epilogue ----
    const int slot = blockIdx.y * 4 + (wid & 3);
#pragma unroll
    for (int am = 0; am < 2; am++) {
        const int m0 = tile_m + wm + am * 16 + g;
        const int m1 = m0 + 8;
        float d0 = 0.f, d1 = 0.f;
#pragma unroll
        for (int bx = 0; bx < 4; bx++) {
            const int col = tile_n + wn + bx * 8 + tg * 2;
            const float bi0 = bias[col], bi1 = bias[col + 1];
            float v00 = acc[am][bx][0] + bi0, v01 = acc[am][bx][1] + bi1;
            float v10 = acc[am][bx][2] + bi0, v11 = acc[am][bx][3] + bi1;
            if (which == 0) {
                const float wa0 = Wa[col], wa1 = Wa[col + 1];
                d0 = fmaf(v00, wa0, fmaf(v01, wa1, d0));
                d1 = fmaf(v10, wa0, fmaf(v11, wa1, d1));
                if (m0 < M)
                    *reinterpret_cast<float2*>(g_src_proj + (long)m0 * OUT_DIM + col) =
                        make_float2(v00, v01);
                if (m1 < M)
                    *reinterpret_cast<float2*>(g_src_proj + (long)m1 * OUT_DIM + col) =
                        make_float2(v10, v11);
            } else {
                if (m0 < M)
                    *reinterpret_cast<__half2*>(g_vals_h + (long)m0 * OUT_DIM + col) =
                        __floats2half2_rn(v00, v01);
                if (m1 < M)
                    *reinterpret_cast<__half2*>(g_vals_h + (long)m1 * OUT_DIM + col) =
                        __floats2half2_rn(v10, v11);
            }
        }
        if (which == 0) {
            d0 += __shfl_xor_sync(0xFFFFFFFFu, d0, 1);
            d0 += __shfl_xor_sync(0xFFFFFFFFu, d0, 2);
            d1 += __shfl_xor_sync(0xFFFFFFFFu, d1, 1);
            d1 += __shfl_xor_sync(0xFFFFFFFFu, d1, 2);
            if (tg == 0) {
                if (m0 < M) g_sdot_part[slot][m0] = d0;
                if (m1 < M) g_sdot_part[slot][m1] = d1;
            }
        }
    }
}

// ---------------- softmax: 2 nodes per warp (16 lanes each) ------------------
__global__ void k_softmax(const void* __restrict__ tidp,
                          const float* __restrict__ ba, int Ns) {
    const int warp = (blockIdx.x * blockDim.x + threadIdx.x) >> 5;
    const int lane = threadIdx.x & 31;
    const int l16 = lane & 15;
    const int n = warp * 2 + (lane >> 4);
    const bool valid = (n < Ns);
    const int is64 = g_idx64;
    const int s0 = valid ? g_seg_start[n] : 0;
    const int s1 = valid ? g_seg_end[n] : 0;

    // sdot partial reduction per 16-lane group: l16 0-7 batch0, 8-15 batch1
    float p = valid ? g_sdot_part[l16 & 7][n * 2 + (l16 >> 3)] : 0.f;
    p += __shfl_xor_sync(0xFFFFFFFFu, p, 1);
    p += __shfl_xor_sync(0xFFFFFFFFu, p, 2);
    p += __shfl_xor_sync(0xFFFFFFFFu, p, 4);
    const int gb = lane & 16;
    const float b0 = ba[0];
    const float sd0 = __shfl_sync(0xFFFFFFFFu, p, gb + 0) + b0;
    const float sd1 = __shfl_sync(0xFFFFFFFFu, p, gb + 8) + b0;

    float d0 = 0.f, d1 = 0.f;
    for (int e = s0 + l16; e < s1; e += 16) {
        int tg = IDX(tidp, e, is64);
        float sc0 = sd0 + g_tdot[tg * 2 + 0];
        float sc1 = sd1 + g_tdot[tg * 2 + 1];
        sc0 = (sc0 >= 0.f) ? sc0 : SLOPE * sc0;
        sc1 = (sc1 >= 0.f) ? sc1 : SLOPE * sc1;
        sc0 = fminf(2.f, fmaxf(-2.f, sc0));
        sc1 = fminf(2.f, fmaxf(-2.f, sc1));
        float e0 = expf(sc0), e1 = expf(sc1);
        g_ex[e * 2 + 0] = e0;
        g_ex[e * 2 + 1] = e1;
        d0 += e0;
        d1 += e1;
    }
#pragma unroll
    for (int st = 8; st; st >>= 1) {
        d0 += __shfl_xor_sync(0xFFFFFFFFu, d0, st);
        d1 += __shfl_xor_sync(0xFFFFFFFFu, d1, st);
    }
    if (valid && l16 == 0) {
        g_denom[n * 2 + 0] = d0;
        g_denom[n * 2 + 1] = d1;
    }
}

// ---------------- aggregation: 8 nodes/block, uint4 loads, hfma2 chains -----
__global__ __launch_bounds__(512) void k_agg(const void* __restrict__ sidp,
                                             const void* __restrict__ tidp,
                                             float* __restrict__ out, int Ns) {
    __shared__ __half2 wsh[2][8][16];    // broadcast (w,w) per batch
    __shared__ int ro[8][16];            // row byte offsets into g_vals_h
    __shared__ int cnts[8];
    const int t = threadIdx.x;
    const int sub = t >> 6;
    const int rest = t & 63;
    const int b = rest >> 5;
    const int o8 = rest & 31;
    const int is64 = g_idx64;

    const int n = blockIdx.x * 8 + sub;
    const bool valid = (n < Ns);
    const int s0 = valid ? g_seg_start[n] : 0;
    const int s1 = valid ? g_seg_end[n] : 0;
    if (rest == 0) cnts[sub] = s1 - s0;
    __syncthreads();
    int cmax = cnts[0];
#pragma unroll
    for (int i = 1; i < 8; i++) cmax = max(cmax, cnts[i]);

    const long outbase = ((long)n * BATCH + b) * OUT_DIM + o8 * 8;

    // 4 interleaved fp16 accumulator sets (4 half2 each)
    __half2 acch[4][4];
#pragma unroll
    for (int s = 0; s < 4; s++)
#pragma unroll
        for (int q = 0; q < 4; q++) acch[s][q] = __float2half2_rn(0.f);

    const char* __restrict__ basep =
        reinterpret_cast<const char*>(g_vals_h) + ((b << 8) + (o8 << 3)) * 2;

    for (int base = 0; base < cmax; base += 16) {
        if (t < 128) {
            const int ss = t >> 4, ii = t & 15;
            const int ns = blockIdx.x * 8 + ss;
            if (ns < Ns) {
                int e = g_seg_start[ns] + base + ii;
                if (e < g_seg_end[ns]) {
                    int j = IDX(tidp, e, is64);          // faithful bug
                    int sj = IDX(sidp, j, is64);
                    float w0 = g_ex[j * 2 + 0] / g_denom[sj * 2 + 0];
                    float w1 = g_ex[j * 2 + 1] / g_denom[sj * 2 + 1];
                    wsh[0][ss][ii] = __float2half2_rn(w0);
                    wsh[1][ss][ii] = __float2half2_rn(w1);
                    ro[ss][ii] = IDX(tidp, j, is64) * (BATCH * OUT_DIM * 2);
                } else {
                    wsh[0][ss][ii] = __float2half2_rn(0.f);
                    wsh[1][ss][ii] = __float2half2_rn(0.f);
                    ro[ss][ii] = 0;
                }
            }
        }
        __syncthreads();
        const int lim = min(16, cmax - base);
#pragma unroll 16
        for (int i = 0; i < lim; i++) {
            const __half2 wh = wsh[b][sub][i];
            uint4 h = *reinterpret_cast<const uint4*>(basep + ro[sub][i]);
            const int s = i & 3;
            acch[s][0] = __hfma2(wh, *reinterpret_cast<__half2*>(&h.x), acch[s][0]);
            acch[s][1] = __hfma2(wh, *reinterpret_cast<__half2*>(&h.y), acch[s][1]);
            acch[s][2] = __hfma2(wh, *reinterpret_cast<__half2*>(&h.z), acch[s][2]);
            acch[s][3] = __hfma2(wh, *reinterpret_cast<__half2*>(&h.w), acch[s][3]);
        }
        __syncthreads();
    }

    if (valid) {
        float4 i0 = *reinterpret_cast<const float4*>(g_src_proj + outbase);
        float4 i1 = *reinterpret_cast<const float4*>(g_src_proj + outbase + 4);
        float acc[8] = {i0.x, i0.y, i0.z, i0.w, i1.x, i1.y, i1.z, i1.w};
#pragma unroll
        for (int s = 0; s < 4; s++) {
#pragma unroll
            for (int q = 0; q < 4; q++) {
                float2 f = __half22float2(acch[s][q]);
                acc[q * 2 + 0] += f.x;
                acc[q * 2 + 1] += f.y;
            }
        }
        *reinterpret_cast<float4*>(out + outbase) =
            make_float4(acc[0], acc[1], acc[2], acc[3]);
        *reinterpret_cast<float4*>(out + outbase + 4) =
            make_float4(acc[4], acc[5], acc[6], acc[7]);
    }
}

extern "C" void kernel_launch(void* const* d_in, const int* in_sizes, int n_in,
                              void* d_out, int out_size) {
    const float* nodes = (const float*)d_in[0];
    const float* Ws    = (const float*)d_in[1];
    const float* bs    = (const float*)d_in[2];
    const float* Wt    = (const float*)d_in[3];
    const float* bt    = (const float*)d_in[4];
    const float* Wv    = (const float*)d_in[5];
    const float* bv    = (const float*)d_in[6];
    const float* Wa    = (const float*)d_in[7];
    const float* ba    = (const float*)d_in[8];
    const void* usrc   = d_in[9];
    const void* utgt   = d_in[10];
    const void* sidp   = d_in[11];
    const void* tidp   = d_in[12];

    const int Ns = in_sizes[9];
    const int Nt = in_sizes[10];
    const int E  = in_sizes[11];
    const int ntot = in_sizes[0];
    float* out = (float*)d_out;

    static int smem_set = 0;
    if (!smem_set) {
        cudaFuncSetAttribute(k_gemm_mma, cudaFuncAttributeMaxDynamicSharedMemorySize,
                             SMH_BYTES);
        smem_set = 1;
    }

    const int Ms = Ns * BATCH;
    const int Mt = Nt * BATCH;
    const int NC = (ntot + 2047) / 2048;
    const int NE = (E + 255) / 256;

    k_prep<<<33 + NC + 128 + NE, 256>>>(usrc, Wt, bt, Wa, nodes, Ws, Wv, sidp,
                                        ntot, NC, E);

    const int Mmax = (Ms > Mt) ? Ms : Mt;
    dim3 gg((Mmax + 127) / 128, OUT_DIM / 128, 2);
    k_gemm_mma<<<gg, 512, SMH_BYTES>>>(usrc, utgt, bs, bv, Wa, Ms, Mt);

    k_softmax<<<(Ns * 16 + 255) / 256, 256>>>(tidp, ba, Ns);

    k_agg<<<(Ns + 7) / 8, 512>>>(sidp, tidp, out, Ns);
}